// round 2
// baseline (speedup 1.0000x reference)
#include <cuda_runtime.h>
#include <math.h>

#define KW   9
#define PAD  4
#define TXL  32          // threads in x (each covers 4 px)
#define TYL  4           // threads in y
#define PXT  4           // pixels per thread (horizontal)
#define TW   (TXL*PXT)   // 128 output tile width
#define TH   TYL         // 4 output tile height
#define SX   (TW + 2*PAD)  // 136
#define SY   (TH + 2*PAD)  // 12
#define HH   256
#define WW   256
#define CC   3

#define INV_DIAG (1.0f / 362.03867196751236f)
#define SIGMA_MIN 0.5f
#define SIGMA_RANGE 9.5f
#define PI_F 3.14159265358979323846f

// map (oy,ox) -> index into the 15 unique r_sq values {0,1,2,4,5,8,9,10,13,16,17,18,20,25,32}
__device__ constexpr int QIDX[9][9] = {
    {14,13,12,10, 9,10,12,13,14},
    {13,11, 8, 7, 6, 7, 8,11,13},
    {12, 8, 5, 4, 3, 4, 5, 8,12},
    {10, 7, 4, 2, 1, 2, 4, 7,10},
    { 9, 6, 3, 1, 0, 1, 3, 6, 9},
    {10, 7, 4, 2, 1, 2, 4, 7,10},
    {12, 8, 5, 4, 3, 4, 5, 8,12},
    {13,11, 8, 7, 6, 7, 8,11,13},
    {14,13,12,10, 9,10,12,13,14},
};

__device__ __forceinline__ void make_weights(float ddx, float ddy, float* w)
{
    const float d2   = ddx * ddx + ddy * ddy;
    const float dist = sqrtf(d2);
    const float s    = SIGMA_MIN + SIGMA_RANGE * (dist * INV_DIAG);
    const float s2   = s * s;
    const float a    = 0.5f / s2;
    const float common = (-1.0f / PI_F) * dist * sqrtf(s) / (s2 * s2);

    const float E   = __expf(-a);
    const float E2  = E  * E,  E4  = E2  * E2, E5  = E4  * E;
    const float E8  = E4 * E4, E9  = E8  * E,  E10 = E8  * E2;
    const float E13 = E8 * E5, E16 = E8  * E8, E17 = E16 * E;
    const float E18 = E16* E2, E20 = E16 * E4, E25 = E16 * E9;
    const float E32 = E16 * E16;

    w[0]  = common;
    w[1]  = common * (1.0f -  1.0f * a) * E;
    w[2]  = common * (1.0f -  2.0f * a) * E2;
    w[3]  = common * (1.0f -  4.0f * a) * E4;
    w[4]  = common * (1.0f -  5.0f * a) * E5;
    w[5]  = common * (1.0f -  8.0f * a) * E8;
    w[6]  = common * (1.0f -  9.0f * a) * E9;
    w[7]  = common * (1.0f - 10.0f * a) * E10;
    w[8]  = common * (1.0f - 13.0f * a) * E13;
    w[9]  = common * (1.0f - 16.0f * a) * E16;
    w[10] = common * (1.0f - 17.0f * a) * E17;
    w[11] = common * (1.0f - 18.0f * a) * E18;
    w[12] = common * (1.0f - 20.0f * a) * E20;
    w[13] = common * (1.0f - 25.0f * a) * E25;
    w[14] = common * (1.0f - 32.0f * a) * E32;
}

__global__ __launch_bounds__(TXL * TYL, 5)
void adaptive_log_conv(const float* __restrict__ x,
                       const float* __restrict__ foa,
                       float* __restrict__ out)
{
    __shared__ __align__(16) float sm[CC][SY][SX];

    const int b   = blockIdx.z;
    const int bx0 = blockIdx.x * TW;
    const int by0 = blockIdx.y * TH;
    const int tid = threadIdx.y * TXL + threadIdx.x;

    const float* xb = x + (size_t)b * CC * HH * WW;

    // cooperative tile load with reflect padding (pad=4, single reflection)
    for (int i = tid; i < CC * SY * SX; i += TXL * TYL) {
        int c   = i / (SY * SX);
        int rem = i - c * (SY * SX);
        int ly  = rem / SX;
        int lx  = rem - ly * SX;
        int gy  = by0 + ly - PAD;
        int gx  = bx0 + lx - PAD;
        gy = (gy < 0) ? -gy : ((gy >= HH) ? (2 * HH - 2 - gy) : gy);
        gx = (gx < 0) ? -gx : ((gx >= WW) ? (2 * WW - 2 - gx) : gx);
        sm[c][ly][lx] = __ldg(&xb[(c * HH + gy) * WW + gx]);
    }
    __syncthreads();

    const int lx  = threadIdx.x;
    const int ly  = threadIdx.y;
    const int px0 = bx0 + PXT * lx;     // first of 4 output pixels
    const int py  = by0 + ly;

    const float fx = foa[b * 2 + 0];
    const float fy = foa[b * 2 + 1];
    const float ddy = (float)py - fy;

    float w[PXT][15];
    #pragma unroll
    for (int j = 0; j < PXT; j++)
        make_weights((float)(px0 + j) - fx, ddy, w[j]);

    float acc[CC][PXT];
    #pragma unroll
    for (int c = 0; c < CC; c++)
        #pragma unroll
        for (int j = 0; j < PXT; j++)
            acc[c][j] = 0.0f;

    #pragma unroll
    for (int c = 0; c < CC; c++) {
        #pragma unroll
        for (int oy = 0; oy < KW; oy++) {
            const float* row = &sm[c][ly + oy][PXT * lx];
            const float4 v0 = *(const float4*)(row + 0);
            const float4 v1 = *(const float4*)(row + 4);
            const float4 v2 = *(const float4*)(row + 8);
            float t[12];
            t[0] = v0.x; t[1] = v0.y; t[2]  = v0.z; t[3]  = v0.w;
            t[4] = v1.x; t[5] = v1.y; t[6]  = v1.z; t[7]  = v1.w;
            t[8] = v2.x; t[9] = v2.y; t[10] = v2.z; t[11] = v2.w;
            #pragma unroll
            for (int j = 0; j < PXT; j++) {
                #pragma unroll
                for (int ox = 0; ox < KW; ox++) {
                    acc[c][j] = fmaf(t[j + ox], w[j][QIDX[oy][ox]], acc[c][j]);
                }
            }
        }
    }

    float* ob = out + (size_t)b * CC * HH * WW;
    #pragma unroll
    for (int c = 0; c < CC; c++) {
        float4 r;
        r.x = acc[c][0]; r.y = acc[c][1]; r.z = acc[c][2]; r.w = acc[c][3];
        *(float4*)&ob[(c * HH + py) * WW + px0] = r;
    }
}

extern "C" void kernel_launch(void* const* d_in, const int* in_sizes, int n_in,
                              void* d_out, int out_size)
{
    const float* x   = (const float*)d_in[0];
    const float* foa = (const float*)d_in[1];
    float* out = (float*)d_out;

    dim3 block(TXL, TYL, 1);
    dim3 grid(WW / TW, HH / TH, 4);
    adaptive_log_conv<<<grid, block>>>(x, foa, out);
}

// round 3
// speedup vs baseline: 1.3499x; 1.3499x over previous
#include <cuda_runtime.h>
#include <math.h>

#define KW   9
#define PAD  4
#define TX   32
#define TY   8
#define PXT  2
#define TW   (TX*PXT)      // 64  output tile width
#define TH   TY            // 8   output tile height
#define SXU  (TW + 2*PAD)  // 72  used smem cols
#define SXP  80            // padded smem row stride (floats)
#define SY   (TH + 2*PAD)  // 16  smem rows
#define HH   256
#define WW   256
#define CC   3

#define INV_DIAG (1.0f / 362.03867196751236f)
#define SIGMA_MIN 0.5f
#define SIGMA_RANGE 9.5f
#define PI_F 3.14159265358979323846f

// (oy,ox) -> index into the 15 unique r_sq values {0,1,2,4,5,8,9,10,13,16,17,18,20,25,32}
__device__ constexpr int QIDX[9][9] = {
    {14,13,12,10, 9,10,12,13,14},
    {13,11, 8, 7, 6, 7, 8,11,13},
    {12, 8, 5, 4, 3, 4, 5, 8,12},
    {10, 7, 4, 2, 1, 2, 4, 7,10},
    { 9, 6, 3, 1, 0, 1, 3, 6, 9},
    {10, 7, 4, 2, 1, 2, 4, 7,10},
    {12, 8, 5, 4, 3, 4, 5, 8,12},
    {13,11, 8, 7, 6, 7, 8,11,13},
    {14,13,12,10, 9,10,12,13,14},
};

__device__ __forceinline__ int reflect_idx(int v) {
    v = (v < 0) ? -v : v;
    return (v >= HH) ? (2 * HH - 2 - v) : v;   // H == W == 256
}

__device__ __forceinline__ void make_weights(float ddx, float ddy, float* w)
{
    const float d2   = ddx * ddx + ddy * ddy;
    const float dist = sqrtf(d2);
    const float s    = SIGMA_MIN + SIGMA_RANGE * (dist * INV_DIAG);
    const float s2   = s * s;
    const float a    = 0.5f / s2;
    const float common = -dist * sqrtf(s) * __fdividef(1.0f, PI_F * s2 * s2);

    const float E   = __expf(-a);
    const float E2  = E  * E,  E4  = E2  * E2, E5  = E4  * E;
    const float E8  = E4 * E4, E9  = E8  * E,  E10 = E8  * E2;
    const float E13 = E8 * E5, E16 = E8  * E8, E17 = E16 * E;
    const float E18 = E16* E2, E20 = E16 * E4, E25 = E16 * E9;
    const float E32 = E16 * E16;

    w[0]  = common;
    w[1]  = common * (1.0f -  1.0f * a) * E;
    w[2]  = common * (1.0f -  2.0f * a) * E2;
    w[3]  = common * (1.0f -  4.0f * a) * E4;
    w[4]  = common * (1.0f -  5.0f * a) * E5;
    w[5]  = common * (1.0f -  8.0f * a) * E8;
    w[6]  = common * (1.0f -  9.0f * a) * E9;
    w[7]  = common * (1.0f - 10.0f * a) * E10;
    w[8]  = common * (1.0f - 13.0f * a) * E13;
    w[9]  = common * (1.0f - 16.0f * a) * E16;
    w[10] = common * (1.0f - 17.0f * a) * E17;
    w[11] = common * (1.0f - 18.0f * a) * E18;
    w[12] = common * (1.0f - 20.0f * a) * E20;
    w[13] = common * (1.0f - 25.0f * a) * E25;
    w[14] = common * (1.0f - 32.0f * a) * E32;
}

__global__ __launch_bounds__(TX * TY, 3)
void adaptive_log_conv(const float* __restrict__ x,
                       const float* __restrict__ foa,
                       float* __restrict__ out)
{
    __shared__ __align__(16) float sm[CC][SY][SXP];

    const int b   = blockIdx.z;
    const int bx0 = blockIdx.x * TW;
    const int by0 = blockIdx.y * TH;
    const int lx  = threadIdx.x;
    const int ly  = threadIdx.y;

    const float* xb = x + (size_t)b * CC * HH * WW;

    // ---- structured tile load: no div/mod, reflect coords hoisted ----
    const int gy0 = reflect_idx(by0 + ly       - PAD);   // smem row ly
    const int gy1 = reflect_idx(by0 + ly + TY  - PAD);   // smem row ly+8
    const int gx0 = reflect_idx(bx0 + lx       - PAD);   // smem col lx
    const int gx1 = reflect_idx(bx0 + lx + 32  - PAD);   // smem col lx+32
    const int gx2 = reflect_idx(bx0 + lx + 64  - PAD);   // smem col lx+64 (if lx<8)
    const bool has3 = (lx < SXU - 64);                   // lx < 8

    #pragma unroll
    for (int c = 0; c < CC; c++) {
        const float* xc = xb + c * HH * WW;
        const float* r0 = xc + gy0 * WW;
        const float* r1 = xc + gy1 * WW;
        sm[c][ly     ][lx     ] = __ldg(&r0[gx0]);
        sm[c][ly     ][lx + 32] = __ldg(&r0[gx1]);
        sm[c][ly + TY][lx     ] = __ldg(&r1[gx0]);
        sm[c][ly + TY][lx + 32] = __ldg(&r1[gx1]);
        if (has3) {
            sm[c][ly     ][lx + 64] = __ldg(&r0[gx2]);
            sm[c][ly + TY][lx + 64] = __ldg(&r1[gx2]);
        }
    }
    __syncthreads();

    const int px0 = bx0 + PXT * lx;
    const int py  = by0 + ly;

    const float fx  = foa[b * 2 + 0];
    const float fy  = foa[b * 2 + 1];
    const float ddy = (float)py - fy;

    float w[PXT][15];
    #pragma unroll
    for (int j = 0; j < PXT; j++)
        make_weights((float)(px0 + j) - fx, ddy, w[j]);

    float acc[CC][PXT];
    #pragma unroll
    for (int c = 0; c < CC; c++)
        #pragma unroll
        for (int j = 0; j < PXT; j++)
            acc[c][j] = 0.0f;

    #pragma unroll
    for (int c = 0; c < CC; c++) {
        #pragma unroll
        for (int oy = 0; oy < KW; oy++) {
            const float* row = &sm[c][ly + oy][PXT * lx];
            const float2 p0 = *(const float2*)(row + 0);
            const float2 p1 = *(const float2*)(row + 2);
            const float2 p2 = *(const float2*)(row + 4);
            const float2 p3 = *(const float2*)(row + 6);
            const float2 p4 = *(const float2*)(row + 8);
            float t[10];
            t[0] = p0.x; t[1] = p0.y; t[2] = p1.x; t[3] = p1.y;
            t[4] = p2.x; t[5] = p2.y; t[6] = p3.x; t[7] = p3.y;
            t[8] = p4.x; t[9] = p4.y;
            #pragma unroll
            for (int ox = 0; ox < KW; ox++) {
                const int q = QIDX[oy][ox];
                acc[c][0] = fmaf(t[ox    ], w[0][q], acc[c][0]);
                acc[c][1] = fmaf(t[ox + 1], w[1][q], acc[c][1]);
            }
        }
    }

    float* ob = out + (size_t)b * CC * HH * WW;
    #pragma unroll
    for (int c = 0; c < CC; c++) {
        float2 r;
        r.x = acc[c][0]; r.y = acc[c][1];
        *(float2*)&ob[(c * HH + py) * WW + px0] = r;
    }
}

extern "C" void kernel_launch(void* const* d_in, const int* in_sizes, int n_in,
                              void* d_out, int out_size)
{
    const float* x   = (const float*)d_in[0];
    const float* foa = (const float*)d_in[1];
    float* out = (float*)d_out;

    dim3 block(TX, TY, 1);
    dim3 grid(WW / TW, HH / TH, 4);
    adaptive_log_conv<<<grid, block>>>(x, foa, out);
}